// round 9
// baseline (speedup 1.0000x reference)
#include <cuda_runtime.h>
#include <math.h>

// Shapes fixed by the problem instance:
// b=4 graphs, n=128 nodes, f=32 features, layer channels 64.
#define BG   4
#define NN   128
#define FF   32
#define ECH  64
#define NP   129     // padding for prepA smem
#define NSQ  (NN*NN)
#define CH   32      // m-chunk size in k_main
#define PADJ 132     // j-row padding in k_main tiles (mult of 4 for float4 stores)

typedef unsigned long long u64;

// ---------------- device scratch ----------------
__device__ float  g_A [BG*NSQ];
__device__ float  g_AT[BG*NSQ];        // A^T
__device__ float4 g_GH[BG*NSQ];        // (G, H, M2, M2^T) at [b][i][j]
__device__ float  g_ra[BG*NN];
__device__ float  g_ca[BG*NN];
__device__ float  g_U [BG*FF*NN];
__device__ float  g_UA[BG*FF*NN];
__device__ float  g_Au[BG*FF*NN];
__device__ float  g_su[BG*FF];

// packed per-(b,e,pos) vectors
__device__ float4 g_P4[BG*ECH*NN];     // (p01, p2c, p3c, 0)
__device__ float4 g_I4[BG*ECH*NN];     // (gI, hI, mI, t14)
__device__ float2 g_I2[BG*ECH*NN];     // (t911, Ri)
__device__ float4 g_J4[BG*ECH*NN];     // (gJ, hJ, mJ, Rj)
__device__ float2 g_J2[BG*ECH*NN];     // (t13, t1012)
__device__ float  g_s [BG*ECH];

__device__ float g_w[7*ECH];
__device__ float g_b2sum;

__device__ __forceinline__ float warpSum(float v) {
    #pragma unroll
    for (int o = 16; o; o >>= 1) v += __shfl_down_sync(0xffffffffu, v, o);
    return v;
}
__device__ __forceinline__ u64 pk2(float lo, float hi) {
    u64 r; asm("mov.b64 %0, {%1, %2};" : "=l"(r) : "f"(lo), "f"(hi)); return r;
}
__device__ __forceinline__ float2 upk2(u64 v) {
    float2 f; asm("mov.b64 {%0, %1}, %2;" : "=f"(f.x), "=f"(f.y) : "l"(v)); return f;
}
__device__ __forceinline__ u64 fma2(u64 a, u64 b, u64 c) {
    u64 d; asm("fma.rn.f32x2 %0, %1, %2, %3;" : "=l"(d) : "l"(a), "l"(b), "l"(c)); return d;
}

// ---------------- fused init: A build (blocks 0..3) + layer-2 weights (4..67) ----
__global__ void __launch_bounds__(256) k_init(const int* __restrict__ ei,
                                              const float* __restrict__ ew,
                                              const int* __restrict__ batch,
                                              const float* __restrict__ c2,
                                              const float* __restrict__ b2,
                                              float* __restrict__ out,
                                              int ne) {
    extern __shared__ float sm[];
    int tid = threadIdx.x;
    if (blockIdx.x < BG) {
        int b = blockIdx.x;
        if (tid == 0) out[b] = 0.0f;     // k_main accumulates atomically
        float4* s4 = (float4*)sm;
        for (int idx = tid; idx < NSQ/4; idx += 256)
            s4[idx] = make_float4(0.f, 0.f, 0.f, 0.f);
        __syncthreads();
        for (int idx = tid; idx < ne; idx += 256) {
            int s = ei[idx];
            int g = batch[s];
            if (g == b) {
                int t = ei[ne + idx];
                int r = s - g*NN;
                int c = t - g*NN;
                atomicAdd(&sm[r*NN + c], ew[idx]);
            }
        }
        __syncthreads();
        float4* d4 = (float4*)(g_A + b*NSQ);
        for (int idx = tid; idx < NSQ/4; idx += 256)
            d4[idx] = s4[idx];
    } else {
        int d = blockIdx.x - BG;
        float* sc2 = sm;            // ECH*20
        __shared__ float cs[20];
        for (int idx = tid; idx < ECH*20; idx += 256)
            sc2[idx] = c2[d*(ECH*20) + idx];
        __syncthreads();
        if (tid < 20) {
            float s = 0.f;
            for (int e = 0; e < ECH; e++) s += sc2[e*20 + tid];
            cs[tid] = s;
        }
        __syncthreads();
        if (tid == 0) {
            float invn = 1.0f / (float)NN;
            g_w[0*ECH + d] = cs[15]+cs[16]+cs[17]+cs[18]+cs[19];
            g_w[1*ECH + d] = cs[5]+cs[6]+cs[7]+cs[8];
            g_w[2*ECH + d] = cs[4]*invn;
            g_w[3*ECH + d] = (cs[9]+cs[10]+cs[11]+cs[12]+cs[13])*invn;
            g_w[4*ECH + d] = cs[14]*invn;
            g_w[5*ECH + d] = (cs[0]+cs[1])*invn;
            g_w[6*ECH + d] = (cs[2]+cs[3])*invn;
        }
        if (d == 0 && tid == 32) {
            float s = 0.f;
            for (int e = 0; e < ECH; e++) s += b2[e];
            g_b2sum = s;
        }
    }
}

// Fused: per (b, 8-row tile): G/H/M2/M2T, AT, UA, Au, ra, ca; tile 0: su + g_U.
__global__ void __launch_bounds__(256, 2) k_prepA(const float* __restrict__ x) {
    extern __shared__ float sm[];
    float* sA = sm;              // [128][NP]
    float* sU = sm + NN*NP;      // [32][NP]
    int b = blockIdx.y, t = blockIdx.x, tid = threadIdx.x;
    const float* Ab = g_A + b*NSQ;
    for (int idx = tid; idx < NSQ; idx += 256)
        sA[(idx >> 7)*NP + (idx & 127)] = Ab[idx];
    for (int idx = tid; idx < FF*NN; idx += 256) {
        int d = idx & 31, m = idx >> 5;
        sU[d*NP + m] = x[(b*NN + m)*FF + d];
    }
    __syncthreads();

    int r = tid >> 5, lane = tid & 31;
    int i = 8*t + r;

    float gv[4] = {0,0,0,0}, hv[4] = {0,0,0,0}, mv[4] = {0,0,0,0}, mt[4] = {0,0,0,0};
    #pragma unroll 4
    for (int k = 0; k < NN; k++) {
        float aik = sA[i*NP + k];
        float aki = sA[k*NP + i];
        #pragma unroll
        for (int q = 0; q < 4; q++) {
            int j = lane + 32*q;
            float ajk = sA[j*NP + k];
            float akj = sA[k*NP + j];
            gv[q] = fmaf(aik, ajk, gv[q]);
            hv[q] = fmaf(aki, akj, hv[q]);
            mv[q] = fmaf(aik, akj, mv[q]);
            mt[q] = fmaf(ajk, aki, mt[q]);
        }
    }
    #pragma unroll
    for (int q = 0; q < 4; q++) {
        int j = lane + 32*q;
        g_GH[b*NSQ + i*NN + j] = make_float4(gv[q], hv[q], mv[q], mt[q]);
        g_AT[b*NSQ + i*NN + j] = sA[j*NP + i];   // AT row i = column i of A
    }

    {
        float p = 0.f;
        #pragma unroll
        for (int q = 0; q < 4; q++) p += sA[i*NP + lane + 32*q];
        p = warpSum(p);
        if (lane == 0) g_ra[b*NN + i] = p;
        float c = 0.f;
        #pragma unroll
        for (int q = 0; q < 4; q++) c += sA[(lane + 32*q)*NP + i];
        c = warpSum(c);
        if (lane == 0) g_ca[b*NN + i] = c;
    }

    {
        int d = tid >> 3, p8 = tid & 7;
        int pos = 8*t + p8;
        float ua = 0.f, au = 0.f;
        #pragma unroll 4
        for (int m = 0; m < NN; m++) {
            float um = sU[d*NP + m];
            ua = fmaf(um, sA[m*NP + pos], ua);
            au = fmaf(sA[pos*NP + m], um, au);
        }
        g_UA[(b*FF + d)*NN + pos] = ua;
        g_Au[(b*FF + d)*NN + pos] = au;
    }

    if (t == 0) {
        for (int idx = tid; idx < FF*NN; idx += 256)
            g_U[b*FF*NN + idx] = sU[(idx >> 7)*NP + (idx & 127)];
        if (tid < FF) {
            float s = 0.f;
            for (int m = 0; m < NN; m++) s += sU[tid*NP + m];
            g_su[b*FF + tid] = s;
        }
    }
}

// per (b, e-pair): smem-staged contraction of coeffs1 with U/UA/Au
__global__ void __launch_bounds__(256, 3) k_prepV(const float* __restrict__ c1) {
    extern __shared__ float sm[];
    float* sU  = sm;              // [32][128]
    float* sUA = sm + 4096;
    float* sAu = sm + 8192;
    float* sra = sm + 12288;      // 128
    float* sca = sm + 12416;      // 128
    float* sc  = sm + 12544;      // 2*64*20

    int b = blockIdx.y, eg = blockIdx.x, tid = threadIdx.x;

    {
        const float4* u4  = (const float4*)(g_U  + b*FF*NN);
        const float4* ua4 = (const float4*)(g_UA + b*FF*NN);
        const float4* au4 = (const float4*)(g_Au + b*FF*NN);
        float4* dU  = (float4*)sU;
        float4* dUA = (float4*)sUA;
        float4* dAu = (float4*)sAu;
        #pragma unroll
        for (int k = 0; k < 4; k++) {
            int idx = tid + 256*k;
            dU [idx] = u4 [idx];
            dUA[idx] = ua4[idx];
            dAu[idx] = au4[idx];
        }
        if (tid < 128) { sra[tid] = g_ra[b*NN + tid]; sca[tid] = g_ca[b*NN + tid]; }
        for (int idx = tid; idx < 2*64*20; idx += 256) {
            int s = idx / 1280, rem = idx - s*1280;
            int d = rem / 20, r = rem - d*20;
            sc[idx] = c1[d*(ECH*20) + (2*eg + s)*20 + r];
        }
    }
    __syncthreads();

    int sub = tid >> 7, i = tid & 127;
    int e = 2*eg + sub;
    const float* scb = sc + sub*1280;

    float p01=0, p2c=0, p3c=0, gI=0, gJ=0, hI=0, hJ=0, mI=0, mJ=0;
    float t14=0, t13=0, t911=0, t1012=0;
    float ri_ra=0, ri_uA=0, ri_n=0, ri_Au=0, ri_ca=0, ri_n2=0;
    float rj_ra=0, rj_uA=0, rj_n=0, rj_Au=0, rj_ca=0, rj_ra2=0, rj_n2=0;

    #pragma unroll 8
    for (int d = 0; d < FF; d++) {
        float u  = sU [d*NN + i];
        float ua = sUA[d*NN + i];
        float au = sAu[d*NN + i];
        const float* cr = scb + d*20;
        const float* cc = scb + (d + 32)*20;
        p01   = fmaf(cr[0] + cr[1], u, p01);
        mI    = fmaf(cr[2], u, mI);
        mJ    = fmaf(cr[3], u, mJ);
        gI    = fmaf(cr[4], u, gI);
        ri_ra = fmaf(cr[5] + cr[13], u, ri_ra);
        rj_ra = fmaf(cr[6], u, rj_ra);
        rj_uA = fmaf(cr[7] + cr[9] + cr[11], ua, rj_uA);
        ri_uA = fmaf(cr[8] + cr[10] + cr[12], ua, ri_uA);
        t14   = fmaf(cr[14], u, t14);
        ri_n  = fmaf(cr[15] + cr[19], u, ri_n);
        rj_n  = fmaf(cr[16], u, rj_n);
        hI    = fmaf(cc[0], u, hI);
        hJ    = fmaf(cc[1], u, hJ);
        p2c   = fmaf(cc[2], u, p2c);
        p3c   = fmaf(cc[3], u, p3c);
        gJ    = fmaf(cc[4], u, gJ);
        ri_Au = fmaf(cc[5], au, ri_Au);
        rj_Au = fmaf(cc[6], au, rj_Au);
        rj_ca = fmaf(cc[7], u, rj_ca);
        ri_ca = fmaf(cc[8], u, ri_ca);
        t911  = fmaf(cc[9] + cc[11], u, t911);
        t1012 = fmaf(cc[10] + cc[12], u, t1012);
        t13   = fmaf(cc[13], u, t13);
        rj_ra2= fmaf(cc[14], u, rj_ra2);
        rj_n2 = fmaf(cc[17] + cc[19], u, rj_n2);
        ri_n2 = fmaf(cc[18], u, ri_n2);
    }
    float rai = sra[i], cai = sca[i];
    float Ri = rai*ri_ra + ri_uA + (float)NN*(ri_n + ri_n2) + ri_Au + cai*ri_ca;
    float Rj = rai*(rj_ra + rj_ra2) + rj_uA + (float)NN*(rj_n + rj_n2) + rj_Au + cai*rj_ca;

    int base = (b*ECH + e)*NN + i;
    g_P4[base] = make_float4(p01, p2c, p3c, 0.f);
    g_I4[base] = make_float4(gI, hI, mI, t14);
    g_I2[base] = make_float2(t911, Ri);
    g_J4[base] = make_float4(gJ, hJ, mJ, Rj);
    g_J2[base] = make_float2(t13, t1012);

    if (i == 0) {
        float s = 0.f;
        for (int d = 0; d < FF; d++) {
            float w = scb[d*20 + 17] + scb[d*20 + 18]
                    + scb[(d+32)*20 + 15] + scb[(d+32)*20 + 16];
            s = fmaf(w, g_su[b*FF + d], s);
        }
        g_s[b*ECH + e] = s;
    }
}

// main fused kernel: one i per block, 3 blocks/SM.
// j-packed f32x2 accumulators; chunked cv/rv tiles (both contiguous LDS.64);
// pre-duplicated p operands (LDS.128 broadcast). Zero pack MOVs in inner loop.
__global__ void __launch_bounds__(256, 3) k_main(const float* __restrict__ bias1,
                                                 float* __restrict__ out) {
    extern __shared__ float sm[];
    float* cvT  = sm;                       // [CH][PADJ]   A[m][j] chunk
    float* rvT  = cvT + CH*PADJ;            // [CH][PADJ]   AT[m][j] chunk
    u64*   p1d  = (u64*)(rvT + CH*PADJ);    // [ECH][CH] duplicated
    u64*   p2d  = p1d + ECH*CH;
    float* sAri = (float*)(p2d + ECH*CH);   // 128: A[i][m]
    float* sAci = sAri + 128;               // 128: A[m][i]
    float* sra  = sAci + 128;               // 128
    float* sca  = sra + 128;                // 128
    float* sw   = sca + 128;                // 7*64
    float* ssv  = sw + 7*ECH;               // 64
    float* sb1  = ssv + ECH;                // 64

    int b = blockIdx.y, i = blockIdx.x, tid = threadIdx.x;
    int te = tid >> 5, tj = tid & 31;

    if (tid < 128) {
        sAri[tid] = g_A [b*NSQ + i*NN + tid];
        sAci[tid] = g_AT[b*NSQ + i*NN + tid];
        sra[tid]  = g_ra[b*NN + tid];
        sca[tid]  = g_ca[b*NN + tid];
    }
    for (int idx = tid; idx < 7*ECH; idx += 256) sw[idx] = g_w[idx];
    if (tid < ECH) { ssv[tid] = g_s[b*ECH + tid]; sb1[tid] = bias1[tid]; }
    __syncthreads();

    u64 acc[8][2];
    #pragma unroll
    for (int e8 = 0; e8 < 8; e8++) { acc[e8][0] = 0ULL; acc[e8][1] = 0ULL; }

    const float4* P4 = g_P4 + b*ECH*NN;

    for (int ch = 0; ch < NN/CH; ch++) {
        int m0 = CH*ch;
        __syncthreads();
        // A tiles: cvT[mm][j] = A[m0+mm][j], rvT[mm][j] = AT[m0+mm][j]
        {
            const float4* Ar  = (const float4*)(g_A  + b*NSQ + m0*NN);
            const float4* ATr = (const float4*)(g_AT + b*NSQ + m0*NN);
            #pragma unroll
            for (int k = 0; k < 4; k++) {
                int idx = tid + 256*k;           // < 1024
                int mm = idx >> 5, jj = idx & 31;
                *(float4*)&cvT[mm*PADJ + 4*jj] = Ar [mm*32 + jj];
                *(float4*)&rvT[mm*PADJ + 4*jj] = ATr[mm*32 + jj];
            }
        }
        // p tiles (duplicated)
        {
            #pragma unroll
            for (int k = 0; k < 8; k++) {
                int idx = tid + 256*k;           // < 2048
                int e = idx >> 5, mm = idx & 31;
                float4 p = __ldg(&P4[e*NN + m0 + mm]);
                float am_i = sAci[m0 + mm];
                float ai_m = sAri[m0 + mm];
                float v1 = fmaf(p.x, am_i, p.y*ai_m);
                float v2 = p.z*am_i;
                p1d[e*CH + mm] = pk2(v1, v1);
                p2d[e*CH + mm] = pk2(v2, v2);
            }
        }
        __syncthreads();

        #pragma unroll 2
        for (int mm = 0; mm < CH; mm += 2) {
            u64 cv[2][2], rv[2][2];
            #pragma unroll
            for (int s = 0; s < 2; s++) {
                #pragma unroll
                for (int q = 0; q < 2; q++) {
                    int j2 = tj + 32*q;
                    cv[s][q] = *(const u64*)&cvT[(mm+s)*PADJ + 2*j2];
                    rv[s][q] = *(const u64*)&rvT[(mm+s)*PADJ + 2*j2];
                }
            }
            #pragma unroll
            for (int e8 = 0; e8 < 8; e8++) {
                int e = te*8 + e8;
                ulonglong2 p1 = *(const ulonglong2*)&p1d[e*CH + mm];
                ulonglong2 p2 = *(const ulonglong2*)&p2d[e*CH + mm];
                #pragma unroll
                for (int q = 0; q < 2; q++) {
                    acc[e8][q] = fma2(p1.x, cv[0][q], fma2(p2.x, rv[0][q], acc[e8][q]));
                    acc[e8][q] = fma2(p1.y, cv[1][q], fma2(p2.y, rv[1][q], acc[e8][q]));
                }
            }
        }
    }

    // epilogue: thread's j values are pairs (2*j2, 2*j2+1), j2 = tj + 32q
    float rai = sra[i], cai = sca[i];
    const float invn = 1.0f / (float)NN;
    float accout = 0.f;

    #pragma unroll
    for (int e8 = 0; e8 < 8; e8++) {
        int e = te*8 + e8;
        int base = (b*ECH + e)*NN;
        float4 I4v = g_I4[base + i];
        float2 I2v = g_I2[base + i];
        float sv = ssv[e], b1 = sb1[e];
        float wT    = sw[0*ECH + e];
        float wTA   = sw[1*ECH + e];
        float wTG   = sw[2*ECH + e];
        float wTzRi = sw[3*ECH + e];
        float wTzRj = sw[4*ECH + e];
        float wTARi = sw[5*ECH + e];
        float wTARj = sw[6*ECH + e];
        #pragma unroll
        for (int q = 0; q < 2; q++) {
            float2 av = upk2(acc[e8][q]);
            int j2 = tj + 32*q;
            #pragma unroll
            for (int s = 0; s < 2; s++) {
                int j = 2*j2 + s;
                float4 gh  = g_GH[b*NSQ + i*NN + j];
                float4 J4v = g_J4[base + j];
                float2 J2v = g_J2[base + j];
                float aij = sAri[j], raj = sra[j], caj = sca[j];
                float accv = s ? av.y : av.x;
                float phi = accv
                    + gh.x * (I4v.x + J4v.x)
                    + gh.y * (I4v.y + J4v.y)
                    + gh.z * I4v.z + gh.w * J4v.z
                    + I2v.y + J4v.w
                    + raj * I4v.w + rai * J2v.x
                    + caj * I2v.x + cai * J2v.y
                    + sv;
                float pre = fmaf(phi, invn, b1);
                float z = __fdividef(1.0f, 1.0f + __expf(-pre));
                float w = wT + wTA*aij + wTG*gh.x
                        + rai * fmaf(wTARi, aij, wTzRi)
                        + raj * fmaf(wTARj, aij, wTzRj);
                accout = fmaf(z, w, accout);
            }
        }
    }

    __shared__ float red[8];
    float v = warpSum(accout);
    if ((tid & 31) == 0) red[tid >> 5] = v;
    __syncthreads();
    if (tid == 0) {
        float s = 0.f;
        #pragma unroll
        for (int w8 = 0; w8 < 8; w8++) s += red[w8];
        if (i == 0) s += (float)NSQ * g_b2sum;
        atomicAdd(&out[b], s * (1.0f / (float)(ECH*NSQ)));
    }
}

// ---------------- launch ----------------
extern "C" void kernel_launch(void* const* d_in, const int* in_sizes, int n_in,
                              void* d_out, int out_size) {
    const float* x   = (const float*)d_in[0];
    const float* ew  = (const float*)d_in[1];
    const float* c1  = (const float*)d_in[2];
    const float* b1  = (const float*)d_in[3];
    const float* c2  = (const float*)d_in[4];
    const float* b2  = (const float*)d_in[5];
    const int*   ei  = (const int*)  d_in[6];
    const int*   bat = (const int*)  d_in[7];
    float* out = (float*)d_out;
    int ne = in_sizes[1];

    const int smemI = NSQ * (int)sizeof(float);                               // 64 KB
    const int smemA = (NN*NP + FF*NP) * (int)sizeof(float);
    const int smemV = (3*FF*NN + 256 + 2*ECH*20) * (int)sizeof(float);
    const int smemM = (2*CH*PADJ + 2*ECH*CH*2 + 4*128 + 7*ECH + 2*ECH) * (int)sizeof(float);

    static bool attr_done = false;
    if (!attr_done) {
        cudaFuncSetAttribute(k_init,  cudaFuncAttributeMaxDynamicSharedMemorySize, smemI);
        cudaFuncSetAttribute(k_prepA, cudaFuncAttributeMaxDynamicSharedMemorySize, smemA);
        cudaFuncSetAttribute(k_prepV, cudaFuncAttributeMaxDynamicSharedMemorySize, smemV);
        cudaFuncSetAttribute(k_main,  cudaFuncAttributeMaxDynamicSharedMemorySize, smemM);
        attr_done = true;
    }

    k_init <<<BG + ECH, 256, smemI>>>(ei, ew, bat, c2, b2, out, ne);
    k_prepA<<<dim3(16, BG), 256, smemA>>>(x);
    k_prepV<<<dim3(ECH/2, BG), 256, smemV>>>(c1);
    k_main <<<dim3(NN, BG), 256, smemM>>>(b1, out);
    (void)n_in; (void)out_size;
}

// round 11
// speedup vs baseline: 1.6671x; 1.6671x over previous
#include <cuda_runtime.h>
#include <math.h>

// Shapes fixed by the problem instance:
// b=4 graphs, n=128 nodes, f=32 features, layer channels 64.
#define BG   4
#define NN   128
#define FF   32
#define ECH  64
#define NP   129     // padding for prepA smem
#define NSQ  (NN*NN)
#define CH   32      // m-chunk size in k_main
#define PADJ 132     // j-row padding in k_main tiles (mult of 4 for float4 stores)

typedef unsigned long long u64;

// ---------------- device scratch ----------------
__device__ float  g_A [BG*NSQ];
__device__ float  g_AT[BG*NSQ];        // A^T
__device__ float4 g_GH[BG*NSQ];        // (G, H, M2, M2^T) at [b][i][j]
__device__ float  g_ra[BG*NN];
__device__ float  g_ca[BG*NN];
__device__ float  g_U [BG*FF*NN];
__device__ float  g_UA[BG*FF*NN];
__device__ float  g_Au[BG*FF*NN];
__device__ float  g_su[BG*FF];

// packed per-(b,e,pos) vectors
__device__ float4 g_P4[BG*ECH*NN];     // (p01, p2c, p3c, 0)
__device__ float4 g_I4[BG*ECH*NN];     // (gI, hI, mI, t14)
__device__ float2 g_I2[BG*ECH*NN];     // (t911, Ri)
__device__ float4 g_J4[BG*ECH*NN];     // (gJ, hJ, mJ, Rj)
__device__ float2 g_J2[BG*ECH*NN];     // (t13, t1012)
__device__ float  g_s [BG*ECH];

__device__ float g_w[7*ECH];
__device__ float g_b2sum;

__device__ __forceinline__ float warpSum(float v) {
    #pragma unroll
    for (int o = 16; o; o >>= 1) v += __shfl_down_sync(0xffffffffu, v, o);
    return v;
}
__device__ __forceinline__ u64 pk2(float lo, float hi) {
    u64 r; asm("mov.b64 %0, {%1, %2};" : "=l"(r) : "f"(lo), "f"(hi)); return r;
}
__device__ __forceinline__ float2 upk2(u64 v) {
    float2 f; asm("mov.b64 {%0, %1}, %2;" : "=f"(f.x), "=f"(f.y) : "l"(v)); return f;
}
__device__ __forceinline__ u64 fma2(u64 a, u64 b, u64 c) {
    u64 d; asm("fma.rn.f32x2 %0, %1, %2, %3;" : "=l"(d) : "l"(a), "l"(b), "l"(c)); return d;
}

// ---------------- fused init: A build (blocks 0..3) + layer-2 weights (4..67) ----
__global__ void __launch_bounds__(256) k_init(const int* __restrict__ ei,
                                              const float* __restrict__ ew,
                                              const int* __restrict__ batch,
                                              const float* __restrict__ c2,
                                              const float* __restrict__ b2,
                                              float* __restrict__ out,
                                              int ne) {
    extern __shared__ float sm[];
    int tid = threadIdx.x;
    if (blockIdx.x < BG) {
        int b = blockIdx.x;
        if (tid == 0) out[b] = 0.0f;     // k_main accumulates atomically
        float4* s4 = (float4*)sm;
        for (int idx = tid; idx < NSQ/4; idx += 256)
            s4[idx] = make_float4(0.f, 0.f, 0.f, 0.f);
        __syncthreads();
        for (int idx = tid; idx < ne; idx += 256) {
            int s = ei[idx];
            int g = batch[s];
            if (g == b) {
                int t = ei[ne + idx];
                int r = s - g*NN;
                int c = t - g*NN;
                atomicAdd(&sm[r*NN + c], ew[idx]);
            }
        }
        __syncthreads();
        float4* d4 = (float4*)(g_A + b*NSQ);
        for (int idx = tid; idx < NSQ/4; idx += 256)
            d4[idx] = s4[idx];
    } else {
        int d = blockIdx.x - BG;
        float* sc2 = sm;            // ECH*20
        __shared__ float cs[20];
        for (int idx = tid; idx < ECH*20; idx += 256)
            sc2[idx] = c2[d*(ECH*20) + idx];
        __syncthreads();
        if (tid < 20) {
            float s = 0.f;
            for (int e = 0; e < ECH; e++) s += sc2[e*20 + tid];
            cs[tid] = s;
        }
        __syncthreads();
        if (tid == 0) {
            float invn = 1.0f / (float)NN;
            g_w[0*ECH + d] = cs[15]+cs[16]+cs[17]+cs[18]+cs[19];
            g_w[1*ECH + d] = cs[5]+cs[6]+cs[7]+cs[8];
            g_w[2*ECH + d] = cs[4]*invn;
            g_w[3*ECH + d] = (cs[9]+cs[10]+cs[11]+cs[12]+cs[13])*invn;
            g_w[4*ECH + d] = cs[14]*invn;
            g_w[5*ECH + d] = (cs[0]+cs[1])*invn;
            g_w[6*ECH + d] = (cs[2]+cs[3])*invn;
        }
        if (d == 0 && tid == 32) {
            float s = 0.f;
            for (int e = 0; e < ECH; e++) s += b2[e];
            g_b2sum = s;
        }
    }
}

// Fused: per (b, 8-row tile): G/H/M2/M2T, AT, UA, Au, ra, ca; tile 0: su + g_U.
__global__ void __launch_bounds__(256, 2) k_prepA(const float* __restrict__ x) {
    extern __shared__ float sm[];
    float* sA = sm;              // [128][NP]
    float* sU = sm + NN*NP;      // [32][NP]
    int b = blockIdx.y, t = blockIdx.x, tid = threadIdx.x;
    const float* Ab = g_A + b*NSQ;
    for (int idx = tid; idx < NSQ; idx += 256)
        sA[(idx >> 7)*NP + (idx & 127)] = Ab[idx];
    for (int idx = tid; idx < FF*NN; idx += 256) {
        int d = idx & 31, m = idx >> 5;
        sU[d*NP + m] = x[(b*NN + m)*FF + d];
    }
    __syncthreads();

    int r = tid >> 5, lane = tid & 31;
    int i = 8*t + r;

    float gv[4] = {0,0,0,0}, hv[4] = {0,0,0,0}, mv[4] = {0,0,0,0}, mt[4] = {0,0,0,0};
    #pragma unroll 4
    for (int k = 0; k < NN; k++) {
        float aik = sA[i*NP + k];
        float aki = sA[k*NP + i];
        #pragma unroll
        for (int q = 0; q < 4; q++) {
            int j = lane + 32*q;
            float ajk = sA[j*NP + k];
            float akj = sA[k*NP + j];
            gv[q] = fmaf(aik, ajk, gv[q]);
            hv[q] = fmaf(aki, akj, hv[q]);
            mv[q] = fmaf(aik, akj, mv[q]);
            mt[q] = fmaf(ajk, aki, mt[q]);
        }
    }
    #pragma unroll
    for (int q = 0; q < 4; q++) {
        int j = lane + 32*q;
        g_GH[b*NSQ + i*NN + j] = make_float4(gv[q], hv[q], mv[q], mt[q]);
        g_AT[b*NSQ + i*NN + j] = sA[j*NP + i];   // AT row i = column i of A
    }

    {
        float p = 0.f;
        #pragma unroll
        for (int q = 0; q < 4; q++) p += sA[i*NP + lane + 32*q];
        p = warpSum(p);
        if (lane == 0) g_ra[b*NN + i] = p;
        float c = 0.f;
        #pragma unroll
        for (int q = 0; q < 4; q++) c += sA[(lane + 32*q)*NP + i];
        c = warpSum(c);
        if (lane == 0) g_ca[b*NN + i] = c;
    }

    {
        int d = tid >> 3, p8 = tid & 7;
        int pos = 8*t + p8;
        float ua = 0.f, au = 0.f;
        #pragma unroll 4
        for (int m = 0; m < NN; m++) {
            float um = sU[d*NP + m];
            ua = fmaf(um, sA[m*NP + pos], ua);
            au = fmaf(sA[pos*NP + m], um, au);
        }
        g_UA[(b*FF + d)*NN + pos] = ua;
        g_Au[(b*FF + d)*NN + pos] = au;
    }

    if (t == 0) {
        for (int idx = tid; idx < FF*NN; idx += 256)
            g_U[b*FF*NN + idx] = sU[(idx >> 7)*NP + (idx & 127)];
        if (tid < FF) {
            float s = 0.f;
            for (int m = 0; m < NN; m++) s += sU[tid*NP + m];
            g_su[b*FF + tid] = s;
        }
    }
}

// per (b, e-pair): smem-staged contraction of coeffs1 with U/UA/Au
__global__ void __launch_bounds__(256, 3) k_prepV(const float* __restrict__ c1) {
    extern __shared__ float sm[];
    float* sU  = sm;              // [32][128]
    float* sUA = sm + 4096;
    float* sAu = sm + 8192;
    float* sra = sm + 12288;      // 128
    float* sca = sm + 12416;      // 128
    float* sc  = sm + 12544;      // 2*64*20

    int b = blockIdx.y, eg = blockIdx.x, tid = threadIdx.x;

    {
        const float4* u4  = (const float4*)(g_U  + b*FF*NN);
        const float4* ua4 = (const float4*)(g_UA + b*FF*NN);
        const float4* au4 = (const float4*)(g_Au + b*FF*NN);
        float4* dU  = (float4*)sU;
        float4* dUA = (float4*)sUA;
        float4* dAu = (float4*)sAu;
        #pragma unroll
        for (int k = 0; k < 4; k++) {
            int idx = tid + 256*k;
            dU [idx] = u4 [idx];
            dUA[idx] = ua4[idx];
            dAu[idx] = au4[idx];
        }
        if (tid < 128) { sra[tid] = g_ra[b*NN + tid]; sca[tid] = g_ca[b*NN + tid]; }
        for (int idx = tid; idx < 2*64*20; idx += 256) {
            int s = idx / 1280, rem = idx - s*1280;
            int d = rem / 20, r = rem - d*20;
            sc[idx] = c1[d*(ECH*20) + (2*eg + s)*20 + r];
        }
    }
    __syncthreads();

    int sub = tid >> 7, i = tid & 127;
    int e = 2*eg + sub;
    const float* scb = sc + sub*1280;

    float p01=0, p2c=0, p3c=0, gI=0, gJ=0, hI=0, hJ=0, mI=0, mJ=0;
    float t14=0, t13=0, t911=0, t1012=0;
    float ri_ra=0, ri_uA=0, ri_n=0, ri_Au=0, ri_ca=0, ri_n2=0;
    float rj_ra=0, rj_uA=0, rj_n=0, rj_Au=0, rj_ca=0, rj_ra2=0, rj_n2=0;

    #pragma unroll 8
    for (int d = 0; d < FF; d++) {
        float u  = sU [d*NN + i];
        float ua = sUA[d*NN + i];
        float au = sAu[d*NN + i];
        const float* cr = scb + d*20;
        const float* cc = scb + (d + 32)*20;
        p01   = fmaf(cr[0] + cr[1], u, p01);
        mI    = fmaf(cr[2], u, mI);
        mJ    = fmaf(cr[3], u, mJ);
        gI    = fmaf(cr[4], u, gI);
        ri_ra = fmaf(cr[5] + cr[13], u, ri_ra);
        rj_ra = fmaf(cr[6], u, rj_ra);
        rj_uA = fmaf(cr[7] + cr[9] + cr[11], ua, rj_uA);
        ri_uA = fmaf(cr[8] + cr[10] + cr[12], ua, ri_uA);
        t14   = fmaf(cr[14], u, t14);
        ri_n  = fmaf(cr[15] + cr[19], u, ri_n);
        rj_n  = fmaf(cr[16], u, rj_n);
        hI    = fmaf(cc[0], u, hI);
        hJ    = fmaf(cc[1], u, hJ);
        p2c   = fmaf(cc[2], u, p2c);
        p3c   = fmaf(cc[3], u, p3c);
        gJ    = fmaf(cc[4], u, gJ);
        ri_Au = fmaf(cc[5], au, ri_Au);
        rj_Au = fmaf(cc[6], au, rj_Au);
        rj_ca = fmaf(cc[7], u, rj_ca);
        ri_ca = fmaf(cc[8], u, ri_ca);
        t911  = fmaf(cc[9] + cc[11], u, t911);
        t1012 = fmaf(cc[10] + cc[12], u, t1012);
        t13   = fmaf(cc[13], u, t13);
        rj_ra2= fmaf(cc[14], u, rj_ra2);
        rj_n2 = fmaf(cc[17] + cc[19], u, rj_n2);
        ri_n2 = fmaf(cc[18], u, ri_n2);
    }
    float rai = sra[i], cai = sca[i];
    float Ri = rai*ri_ra + ri_uA + (float)NN*(ri_n + ri_n2) + ri_Au + cai*ri_ca;
    float Rj = rai*(rj_ra + rj_ra2) + rj_uA + (float)NN*(rj_n + rj_n2) + rj_Au + cai*rj_ca;

    int base = (b*ECH + e)*NN + i;
    g_P4[base] = make_float4(p01, p2c, p3c, 0.f);
    g_I4[base] = make_float4(gI, hI, mI, t14);
    g_I2[base] = make_float2(t911, Ri);
    g_J4[base] = make_float4(gJ, hJ, mJ, Rj);
    g_J2[base] = make_float2(t13, t1012);

    if (i == 0) {
        float s = 0.f;
        for (int d = 0; d < FF; d++) {
            float w = scb[d*20 + 17] + scb[d*20 + 18]
                    + scb[(d+32)*20 + 15] + scb[(d+32)*20 + 16];
            s = fmaf(w, g_su[b*FF + d], s);
        }
        g_s[b*ECH + e] = s;
    }
}

// main fused kernel: one i per block, 2 blocks/SM (NO tighter bound -> no spills).
// j-packed f32x2 accumulators; chunked cv/rv tiles (contiguous LDS.64);
// pre-duplicated p operands (LDS.128 broadcast). Zero pack MOVs in inner loop.
__global__ void __launch_bounds__(256, 2) k_main(const float* __restrict__ bias1,
                                                 float* __restrict__ out) {
    extern __shared__ float sm[];
    float* cvT  = sm;                       // [CH][PADJ]   A[m][j] chunk
    float* rvT  = cvT + CH*PADJ;            // [CH][PADJ]   AT[m][j] chunk
    u64*   p1d  = (u64*)(rvT + CH*PADJ);    // [ECH][CH] duplicated
    u64*   p2d  = p1d + ECH*CH;
    float* sAri = (float*)(p2d + ECH*CH);   // 128: A[i][m]
    float* sAci = sAri + 128;               // 128: A[m][i]
    float* sra  = sAci + 128;               // 128
    float* sca  = sra + 128;                // 128
    float* sw   = sca + 128;                // 7*64
    float* ssv  = sw + 7*ECH;               // 64
    float* sb1  = ssv + ECH;                // 64

    int b = blockIdx.y, i = blockIdx.x, tid = threadIdx.x;
    int te = tid >> 5, tj = tid & 31;

    if (tid < 128) {
        sAri[tid] = g_A [b*NSQ + i*NN + tid];
        sAci[tid] = g_AT[b*NSQ + i*NN + tid];
        sra[tid]  = g_ra[b*NN + tid];
        sca[tid]  = g_ca[b*NN + tid];
    }
    for (int idx = tid; idx < 7*ECH; idx += 256) sw[idx] = g_w[idx];
    if (tid < ECH) { ssv[tid] = g_s[b*ECH + tid]; sb1[tid] = bias1[tid]; }
    __syncthreads();

    u64 acc[8][2];
    #pragma unroll
    for (int e8 = 0; e8 < 8; e8++) { acc[e8][0] = 0ULL; acc[e8][1] = 0ULL; }

    const float4* P4 = g_P4 + b*ECH*NN;

    for (int ch = 0; ch < NN/CH; ch++) {
        int m0 = CH*ch;
        __syncthreads();
        // A tiles: cvT[mm][j] = A[m0+mm][j], rvT[mm][j] = AT[m0+mm][j]
        {
            const float4* Ar  = (const float4*)(g_A  + b*NSQ + m0*NN);
            const float4* ATr = (const float4*)(g_AT + b*NSQ + m0*NN);
            #pragma unroll
            for (int k = 0; k < 4; k++) {
                int idx = tid + 256*k;           // < 1024
                int mm = idx >> 5, jj = idx & 31;
                *(float4*)&cvT[mm*PADJ + 4*jj] = Ar [mm*32 + jj];
                *(float4*)&rvT[mm*PADJ + 4*jj] = ATr[mm*32 + jj];
            }
        }
        // p tiles (duplicated)
        {
            #pragma unroll
            for (int k = 0; k < 8; k++) {
                int idx = tid + 256*k;           // < 2048
                int e = idx >> 5, mm = idx & 31;
                float4 p = __ldg(&P4[e*NN + m0 + mm]);
                float am_i = sAci[m0 + mm];
                float ai_m = sAri[m0 + mm];
                float v1 = fmaf(p.x, am_i, p.y*ai_m);
                float v2 = p.z*am_i;
                p1d[e*CH + mm] = pk2(v1, v1);
                p2d[e*CH + mm] = pk2(v2, v2);
            }
        }
        __syncthreads();

        #pragma unroll 2
        for (int mm = 0; mm < CH; mm += 2) {
            u64 cv[2][2], rv[2][2];
            #pragma unroll
            for (int s = 0; s < 2; s++) {
                #pragma unroll
                for (int q = 0; q < 2; q++) {
                    int j2 = tj + 32*q;
                    cv[s][q] = *(const u64*)&cvT[(mm+s)*PADJ + 2*j2];
                    rv[s][q] = *(const u64*)&rvT[(mm+s)*PADJ + 2*j2];
                }
            }
            #pragma unroll
            for (int e8 = 0; e8 < 8; e8++) {
                int e = te*8 + e8;
                ulonglong2 p1 = *(const ulonglong2*)&p1d[e*CH + mm];
                ulonglong2 p2 = *(const ulonglong2*)&p2d[e*CH + mm];
                #pragma unroll
                for (int q = 0; q < 2; q++) {
                    acc[e8][q] = fma2(p1.x, cv[0][q], fma2(p2.x, rv[0][q], acc[e8][q]));
                    acc[e8][q] = fma2(p1.y, cv[1][q], fma2(p2.y, rv[1][q], acc[e8][q]));
                }
            }
        }
    }

    // epilogue: thread's j values are pairs (2*j2, 2*j2+1), j2 = tj + 32q
    float rai = sra[i], cai = sca[i];
    const float invn = 1.0f / (float)NN;
    float accout = 0.f;

    #pragma unroll
    for (int e8 = 0; e8 < 8; e8++) {
        int e = te*8 + e8;
        int base = (b*ECH + e)*NN;
        float4 I4v = g_I4[base + i];
        float2 I2v = g_I2[base + i];
        float sv = ssv[e], b1 = sb1[e];
        float wT    = sw[0*ECH + e];
        float wTA   = sw[1*ECH + e];
        float wTG   = sw[2*ECH + e];
        float wTzRi = sw[3*ECH + e];
        float wTzRj = sw[4*ECH + e];
        float wTARi = sw[5*ECH + e];
        float wTARj = sw[6*ECH + e];
        #pragma unroll
        for (int q = 0; q < 2; q++) {
            float2 av = upk2(acc[e8][q]);
            int j2 = tj + 32*q;
            #pragma unroll
            for (int s = 0; s < 2; s++) {
                int j = 2*j2 + s;
                float4 gh  = g_GH[b*NSQ + i*NN + j];
                float4 J4v = g_J4[base + j];
                float2 J2v = g_J2[base + j];
                float aij = sAri[j], raj = sra[j], caj = sca[j];
                float accv = s ? av.y : av.x;
                float phi = accv
                    + gh.x * (I4v.x + J4v.x)
                    + gh.y * (I4v.y + J4v.y)
                    + gh.z * I4v.z + gh.w * J4v.z
                    + I2v.y + J4v.w
                    + raj * I4v.w + rai * J2v.x
                    + caj * I2v.x + cai * J2v.y
                    + sv;
                float pre = fmaf(phi, invn, b1);
                float z = __fdividef(1.0f, 1.0f + __expf(-pre));
                float w = wT + wTA*aij + wTG*gh.x
                        + rai * fmaf(wTARi, aij, wTzRi)
                        + raj * fmaf(wTARj, aij, wTzRj);
                accout = fmaf(z, w, accout);
            }
        }
    }

    __shared__ float red[8];
    float v = warpSum(accout);
    if ((tid & 31) == 0) red[tid >> 5] = v;
    __syncthreads();
    if (tid == 0) {
        float s = 0.f;
        #pragma unroll
        for (int w8 = 0; w8 < 8; w8++) s += red[w8];
        if (i == 0) s += (float)NSQ * g_b2sum;
        atomicAdd(&out[b], s * (1.0f / (float)(ECH*NSQ)));
    }
}

// ---------------- launch ----------------
extern "C" void kernel_launch(void* const* d_in, const int* in_sizes, int n_in,
                              void* d_out, int out_size) {
    const float* x   = (const float*)d_in[0];
    const float* ew  = (const float*)d_in[1];
    const float* c1  = (const float*)d_in[2];
    const float* b1  = (const float*)d_in[3];
    const float* c2  = (const float*)d_in[4];
    const float* b2  = (const float*)d_in[5];
    const int*   ei  = (const int*)  d_in[6];
    const int*   bat = (const int*)  d_in[7];
    float* out = (float*)d_out;
    int ne = in_sizes[1];

    const int smemI = NSQ * (int)sizeof(float);                               // 64 KB
    const int smemA = (NN*NP + FF*NP) * (int)sizeof(float);
    const int smemV = (3*FF*NN + 256 + 2*ECH*20) * (int)sizeof(float);
    const int smemM = (2*CH*PADJ + 2*ECH*CH*2 + 4*128 + 7*ECH + 2*ECH) * (int)sizeof(float);

    static bool attr_done = false;
    if (!attr_done) {
        cudaFuncSetAttribute(k_init,  cudaFuncAttributeMaxDynamicSharedMemorySize, smemI);
        cudaFuncSetAttribute(k_prepA, cudaFuncAttributeMaxDynamicSharedMemorySize, smemA);
        cudaFuncSetAttribute(k_prepV, cudaFuncAttributeMaxDynamicSharedMemorySize, smemV);
        cudaFuncSetAttribute(k_main,  cudaFuncAttributeMaxDynamicSharedMemorySize, smemM);
        attr_done = true;
    }

    k_init <<<BG + ECH, 256, smemI>>>(ei, ew, bat, c2, b2, out, ne);
    k_prepA<<<dim3(16, BG), 256, smemA>>>(x);
    k_prepV<<<dim3(ECH/2, BG), 256, smemV>>>(c1);
    k_main <<<dim3(NN, BG), 256, smemM>>>(b1, out);
    (void)n_in; (void)out_size;
}